// round 15
// baseline (speedup 1.0000x reference)
#include <cuda_runtime.h>
#include <cuda_fp16.h>
#include <mma.h>
#include <cstdint>
#include <cstddef>

using namespace nvcuda;

#define Bz 16
#define Sz 512
#define Hz 768
#define Lz 12
#define NHz 12
#define Iz 3072
#define DHz 64
#define BSHz (Bz*Sz*Hz)
#define QLD 2304

// ---------------- scratch (device globals; no allocations allowed) ----------
__device__ __align__(16) float  g_x[BSHz];        // fp32 residual master (attn input)
__device__ __align__(16) float  g_attn[BSHz];     // fp32 residual master (FFN input)
__device__ __align__(16) float  g_tmp[BSHz];      // split-K partial 0 (incl. residual)
__device__ __align__(16) float  g_tmp2[BSHz];     // split-K partial 1
__device__ __align__(16) float  g_tmp3[BSHz];     // split-K partial 2 (FFN2 split-3)
__device__ __align__(16) __half g_xb[BSHz];
__device__ __align__(16) __half g_attnb[BSHz];
__device__ __align__(16) __half g_qkv[3*BSHz];            // [8192][2304]
__device__ __align__(16) __half g_ctx[BSHz];
__device__ __align__(16) __half g_h[(size_t)Bz*Sz*Iz];
__device__ __align__(16) __half g_wqkvT[(size_t)Lz*3*Hz*Hz];   // [L][2304][768]
__device__ __align__(16) __half g_woT[(size_t)Lz*Hz*Hz];       // [L][768][768]
__device__ __align__(16) __half g_wiT[(size_t)Lz*Hz*Iz];       // [L][3072][768]
__device__ __align__(16) __half g_wo2T[(size_t)Lz*Hz*Iz];      // [L][768][3072]

// ---------------- cp.async helpers ------------------------------------------
__device__ __forceinline__ void cpa16(uint32_t d, const void* s) {
    asm volatile("cp.async.cg.shared.global [%0], [%1], 16;" :: "r"(d), "l"(s));
}
__device__ __forceinline__ void cpa_commit() { asm volatile("cp.async.commit_group;"); }
template<int N> __device__ __forceinline__ void cpa_wait() {
    asm volatile("cp.async.wait_group %0;" :: "n"(N));
}

// ---------------- mma / ldmatrix helpers -------------------------------------
__device__ __forceinline__ void ldsm4(uint32_t* r, uint32_t a) {
    asm volatile("ldmatrix.sync.aligned.m8n8.x4.shared.b16 {%0,%1,%2,%3}, [%4];"
        : "=r"(r[0]), "=r"(r[1]), "=r"(r[2]), "=r"(r[3]) : "r"(a));
}
__device__ __forceinline__ void ldsm4t(uint32_t* r, uint32_t a) {
    asm volatile("ldmatrix.sync.aligned.m8n8.x4.trans.shared.b16 {%0,%1,%2,%3}, [%4];"
        : "=r"(r[0]), "=r"(r[1]), "=r"(r[2]), "=r"(r[3]) : "r"(a));
}
__device__ __forceinline__ void mma16816(float* c, const uint32_t* a, uint32_t b0, uint32_t b1) {
    asm volatile("mma.sync.aligned.m16n8k16.row.col.f32.f16.f16.f32 "
        "{%0,%1,%2,%3}, {%4,%5,%6,%7}, {%8,%9}, {%0,%1,%2,%3};"
        : "+f"(c[0]), "+f"(c[1]), "+f"(c[2]), "+f"(c[3])
        : "r"(a[0]), "r"(a[1]), "r"(a[2]), "r"(a[3]), "r"(b0), "r"(b1));
}

// ---------------- weight transpose + fp32->fp16 ------------------------------
__global__ void transpose_f2h_k(const float* __restrict__ src, __half* __restrict__ dst,
                                int R, int C) {
    __shared__ float t[32][33];
    int bx = blockIdx.x * 32, by = blockIdx.y * 32;
    const float* s = src + (size_t)blockIdx.z * R * C;
    __half* d = dst + (size_t)blockIdx.z * R * C;
    int tx = threadIdx.x, ty = threadIdx.y;
    #pragma unroll
    for (int i = 0; i < 32; i += 8)
        t[ty + i][tx] = s[(size_t)(by + ty + i) * C + bx + tx];
    __syncthreads();
    #pragma unroll
    for (int i = 0; i < 32; i += 8)
        d[(size_t)(bx + ty + i) * R + by + tx] = __float2half_rn(t[tx][ty + i]);
}

// QKV: 3 sources -> [L][2304][768] fp16 (each slot transposed)
__global__ void transpose_qkv_k(const float* __restrict__ q, const float* __restrict__ k,
                                const float* __restrict__ v, __half* __restrict__ dst) {
    __shared__ float t[32][33];
    int z = blockIdx.z;
    int slot = z / Lz, l = z % Lz;
    const float* srcs = (slot == 0 ? q : (slot == 1 ? k : v)) + (size_t)l * Hz * Hz;
    __half* d = dst + ((size_t)l * 3 + slot) * Hz * Hz;
    int bx = blockIdx.x * 32, by = blockIdx.y * 32;
    int tx = threadIdx.x, ty = threadIdx.y;
    #pragma unroll
    for (int i = 0; i < 32; i += 8)
        t[ty + i][tx] = srcs[(size_t)(by + ty + i) * Hz + bx + tx];
    __syncthreads();
    #pragma unroll
    for (int i = 0; i < 32; i += 8)
        d[(size_t)(bx + ty + i) * Hz + by + tx] = __float2half_rn(t[tx][ty + i]);
}

// ---------------- block reductions ------------------------------------------
__device__ __forceinline__ float bsum256(float v, float* sm) {
    #pragma unroll
    for (int o = 16; o; o >>= 1) v += __shfl_xor_sync(0xFFFFFFFFu, v, o);
    int t = threadIdx.x;
    if ((t & 31) == 0) sm[t >> 5] = v;
    __syncthreads();
    float r = sm[0];
    #pragma unroll
    for (int i = 1; i < 8; i++) r += sm[i];
    __syncthreads();
    return r;
}

// ---------------- embedding + LN ---------------------------------------------
__global__ void embed_ln_k(const int* __restrict__ ids,
                           const float* __restrict__ we,
                           const float* __restrict__ pe,
                           const float* __restrict__ te,
                           const float* __restrict__ g,
                           const float* __restrict__ b,
                           float* __restrict__ dF,
                           __half* __restrict__ dB) {
    __shared__ float sm[8];
    int row = blockIdx.x;
    int s_ = row & (Sz - 1);
    int id = ids[row];
    int t = threadIdx.x;
    float v[3];
    #pragma unroll
    for (int i = 0; i < 3; i++) {
        int col = t + i * 256;
        v[i] = we[(size_t)id * Hz + col] + pe[(size_t)(s_ + 2) * Hz + col] + te[col];
    }
    float mean = bsum256(v[0] + v[1] + v[2], sm) * (1.0f / Hz);
    float d0 = v[0] - mean, d1 = v[1] - mean, d2 = v[2] - mean;
    float var = bsum256(d0*d0 + d1*d1 + d2*d2, sm) * (1.0f / Hz);
    float rs = rsqrtf(var + 1e-5f);
    size_t base = (size_t)row * Hz;
    #pragma unroll
    for (int i = 0; i < 3; i++) {
        int col = t + i * 256;
        float y = (v[i] - mean) * rs * g[col] + b[col];
        dF[base + col] = y;
        dB[base + col] = __float2half_rn(y);
    }
}

// ---------------- fused split-K reduce + bias + LayerNorm --------------------
// residual already folded into p0 (GEMM accumulator init). p2 may be null.
__global__ void lnr_k(const float* __restrict__ p0,
                      const float* __restrict__ p1,
                      const float* __restrict__ p2,
                      const float* __restrict__ bias,
                      const float* __restrict__ g,
                      const float* __restrict__ b,
                      float* __restrict__ dF,
                      __half* __restrict__ dB) {
    __shared__ float sm[8];
    size_t base = (size_t)blockIdx.x * Hz;
    int t = threadIdx.x;
    float v[3];
    #pragma unroll
    for (int i = 0; i < 3; i++) {
        int col = t + i * 256;
        float s = p0[base + col] + p1[base + col];
        if (p2) s += p2[base + col];
        v[i] = s + bias[col];
    }
    float mean = bsum256(v[0] + v[1] + v[2], sm) * (1.0f / Hz);
    float d0 = v[0] - mean, d1 = v[1] - mean, d2 = v[2] - mean;
    float var = bsum256(d0*d0 + d1*d1 + d2*d2, sm) * (1.0f / Hz);
    float rs = rsqrtf(var + 1e-5f);
    #pragma unroll
    for (int i = 0; i < 3; i++) {
        int col = t + i * 256;
        float y = (v[i] - mean) * rs * g[col] + b[col];
        dF[base + col] = y;
        dB[base + col] = __float2half_rn(y);
    }
}

// ---------------- HMMA GEMM: 128x128 tile, 4 warps of 64x64, BK=64, 3-stage --
// A [M, lda] fp16, uses cols [z*K, z*K+K). Bt [N, lda] same. grid (N/128, M/128, splits).
// EPI: 0 outB = half(acc + bias)   (bias1/bias2: QKV slot biases by column)
//      3 raw fp32 acc -> outF[zi], direct fragment stores; zi==0 acc init from res
struct GP {
    const __half* A;
    const __half* Bt;
    const float* bias;
    const float* bias1;
    const float* bias2;
    const float* res;      // fp32 residual, acc-init for EPI=3, zi==0
    float* outF;
    float* outF2;
    float* outF3;
    __half* outB;
    int K, lda, ldo;
};

#define GSMEM 110592

template<int EPI>
__global__ void __launch_bounds__(128, 2) hgemm_k(GP p) {
    extern __shared__ __align__(16) char smraw[];
    const int tid = threadIdx.x;
    const int wid = tid >> 5;
    const int wm = wid >> 1, wn = wid & 1;     // 2x2 warp grid, 64x64 each
    const int m0 = blockIdx.y * 128, n0 = blockIdx.x * 128;
    const int zi = blockIdx.z;

    const __half* Arow = p.A + (size_t)m0 * p.lda + (size_t)zi * p.K;
    const __half* Brow = p.Bt + (size_t)n0 * p.lda + (size_t)zi * p.K;
    const int K = p.K, KT = K >> 6, lda = p.lda;

    uint32_t sbase = (uint32_t)__cvta_generic_to_shared(smraw);

    auto issue = [&](int kt, int st) {
        const __half* as = Arow + kt * 64;
        const __half* bs = Brow + kt * 64;
        const uint32_t sa = sbase + st * 36864;
        const uint32_t sb = sa + 18432;
        #pragma unroll
        for (int i = 0; i < 8; i++) {
            int g = tid + i * 128;
            int r = g >> 3, c = g & 7;
            cpa16(sa + r * 144 + c * 16, as + (size_t)r * lda + c * 8);
            cpa16(sb + r * 144 + c * 16, bs + (size_t)r * lda + c * 8);
        }
    };

    issue(0, 0); cpa_commit();
    issue(1, 1); cpa_commit();

    wmma::fragment<wmma::accumulator, 16, 16, 16, float> acc[4][4];
    if (EPI == 3 && zi == 0 && p.res) {
        // fold residual into the accumulator (read hidden under GEMM compute)
        const float* rb = p.res + (size_t)m0 * p.ldo + n0;
        #pragma unroll
        for (int i = 0; i < 4; i++)
            #pragma unroll
            for (int j = 0; j < 4; j++)
                wmma::load_matrix_sync(acc[i][j],
                    rb + (size_t)(wm * 64 + i * 16) * p.ldo + wn * 64 + j * 16,
                    p.ldo, wmma::mem_row_major);
    } else {
        #pragma unroll
        for (int i = 0; i < 4; i++)
            #pragma unroll
            for (int j = 0; j < 4; j++) wmma::fill_fragment(acc[i][j], 0.0f);
    }

    for (int kt = 0; kt < KT; kt++) {
        cpa_wait<1>();
        __syncthreads();
        if (kt + 2 < KT) issue(kt + 2, (kt + 2) % 3);
        cpa_commit();

        const int st = kt % 3;
        const __half* sA = (const __half*)(smraw + st * 36864);
        const __half* sB = sA + 9216;
        #pragma unroll
        for (int kk = 0; kk < 4; kk++) {
            wmma::fragment<wmma::matrix_a, 16, 16, 16, __half, wmma::row_major> af[4];
            #pragma unroll
            for (int i = 0; i < 4; i++)
                wmma::load_matrix_sync(af[i], sA + (wm * 64 + i * 16) * 72 + kk * 16, 72);
            wmma::fragment<wmma::matrix_b, 16, 16, 16, __half, wmma::col_major> bf[4];
            #pragma unroll
            for (int j = 0; j < 4; j++)
                wmma::load_matrix_sync(bf[j], sB + (wn * 64 + j * 16) * 72 + kk * 16, 72);
            #pragma unroll
            for (int i = 0; i < 4; i++)
                #pragma unroll
                for (int j = 0; j < 4; j++)
                    wmma::mma_sync(acc[i][j], af[i], bf[j], acc[i][j]);
        }
    }

    if (EPI == 3) {
        float* outp = (zi == 0) ? p.outF : ((zi == 1) ? p.outF2 : p.outF3);
        float* out = outp + (size_t)m0 * p.ldo + n0;
        #pragma unroll
        for (int i = 0; i < 4; i++)
            #pragma unroll
            for (int j = 0; j < 4; j++)
                wmma::store_matrix_sync(out + (size_t)(wm * 64 + i * 16) * p.ldo + wn * 64 + j * 16,
                                        acc[i][j], p.ldo, wmma::mem_row_major);
        return;
    }

    __syncthreads();
    float* epi = (float*)smraw;
    #pragma unroll
    for (int i = 0; i < 4; i++)
        #pragma unroll
        for (int j = 0; j < 4; j++)
            wmma::store_matrix_sync(epi + (wm * 64 + i * 16) * 132 + wn * 64 + j * 16,
                                    acc[i][j], 132, wmma::mem_row_major);
    __syncthreads();

    {
        const float* ep = epi + tid * 132;
        const int gm = m0 + tid;
        __half* orow = p.outB + (size_t)gm * p.ldo + n0;
        #pragma unroll 4
        for (int c0 = 0; c0 < 128; c0 += 8) {
            float f[8];
            #pragma unroll
            for (int j = 0; j < 8; j++) {
                int n = n0 + c0 + j;
                float bv;
                if (EPI == 0 && p.bias1) {
                    const float* bp = n < 768 ? p.bias : (n < 1536 ? p.bias1 : p.bias2);
                    bv = bp[n & 767];
                } else {
                    bv = p.bias[n];
                }
                f[j] = ep[c0 + j] + bv;
            }
            __half2 h[4];
            #pragma unroll
            for (int j = 0; j < 4; j++) h[j] = __floats2half2_rn(f[2*j], f[2*j+1]);
            *(uint4*)(orow + c0) = *(uint4*)h;
        }
    }
}

// ---------------- FFN1 GEMM: 64x128 tile, 4 warps of 32x64, BK=64, 2-stage ---
// occupancy 3 -> 444 blocks/wave; 3072 blocks = 6.92->7 waves (98.8% wave eff).
// outB = half(gelu(acc + bias))
#define G64SMEM 55296

__global__ void __launch_bounds__(128, 3) hgemm64_k(GP p) {
    extern __shared__ __align__(16) char smraw[];
    const int tid = threadIdx.x;
    const int wid = tid >> 5;
    const int wm = wid >> 1, wn = wid & 1;     // 2x2 warp grid, 32x64 each
    const int m0 = blockIdx.y * 64, n0 = blockIdx.x * 128;

    const __half* Arow = p.A + (size_t)m0 * p.lda;
    const __half* Brow = p.Bt + (size_t)n0 * p.lda;
    const int K = p.K, KT = K >> 6, lda = p.lda;

    uint32_t sbase = (uint32_t)__cvta_generic_to_shared(smraw);

    auto issue = [&](int kt, int st) {
        const __half* as = Arow + kt * 64;
        const __half* bs = Brow + kt * 64;
        const uint32_t sa = sbase + st * 27648;
        const uint32_t sb = sa + 9216;
        #pragma unroll
        for (int i = 0; i < 4; i++) {
            int g = tid + i * 128;
            int r = g >> 3, c = g & 7;
            cpa16(sa + r * 144 + c * 16, as + (size_t)r * lda + c * 8);
        }
        #pragma unroll
        for (int i = 0; i < 8; i++) {
            int g = tid + i * 128;
            int r = g >> 3, c = g & 7;
            cpa16(sb + r * 144 + c * 16, bs + (size_t)r * lda + c * 8);
        }
    };

    issue(0, 0); cpa_commit();

    wmma::fragment<wmma::accumulator, 16, 16, 16, float> acc[2][4];
    #pragma unroll
    for (int i = 0; i < 2; i++)
        #pragma unroll
        for (int j = 0; j < 4; j++) wmma::fill_fragment(acc[i][j], 0.0f);

    for (int kt = 0; kt < KT; kt++) {
        cpa_wait<0>();
        __syncthreads();
        if (kt + 1 < KT) { issue(kt + 1, (kt + 1) & 1); cpa_commit(); }

        const int st = kt & 1;
        const __half* sA = (const __half*)(smraw + st * 27648);
        const __half* sB = sA + 4608;
        #pragma unroll
        for (int kk = 0; kk < 4; kk++) {
            wmma::fragment<wmma::matrix_a, 16, 16, 16, __half, wmma::row_major> af[2];
            #pragma unroll
            for (int i = 0; i < 2; i++)
                wmma::load_matrix_sync(af[i], sA + (wm * 32 + i * 16) * 72 + kk * 16, 72);
            wmma::fragment<wmma::matrix_b, 16, 16, 16, __half, wmma::col_major> bf[4];
            #pragma unroll
            for (int j = 0; j < 4; j++)
                wmma::load_matrix_sync(bf[j], sB + (wn * 64 + j * 16) * 72 + kk * 16, 72);
            #pragma unroll
            for (int i = 0; i < 2; i++)
                #pragma unroll
                for (int j = 0; j < 4; j++)
                    wmma::mma_sync(acc[i][j], af[i], bf[j], acc[i][j]);
        }
        __syncthreads();
    }

    float* epi = (float*)smraw;
    #pragma unroll
    for (int i = 0; i < 2; i++)
        #pragma unroll
        for (int j = 0; j < 4; j++)
            wmma::store_matrix_sync(epi + (wm * 32 + i * 16) * 132 + wn * 64 + j * 16,
                                    acc[i][j], 132, wmma::mem_row_major);
    __syncthreads();

    {
        const int r = tid >> 1;
        const int co = (tid & 1) * 64;
        const float* ep = epi + r * 132 + co;
        const int gm = m0 + r;
        const int gn0 = n0 + co;
        __half* orow = p.outB + (size_t)gm * p.ldo + gn0;
        #pragma unroll 4
        for (int c0 = 0; c0 < 64; c0 += 8) {
            float f[8];
            #pragma unroll
            for (int j = 0; j < 8; j++) f[j] = ep[c0 + j] + p.bias[gn0 + c0 + j];
            #pragma unroll
            for (int j = 0; j < 8; j++)
                f[j] = 0.5f * f[j] * (1.0f + erff(f[j] * 0.70710678118654752f));
            __half2 h[4];
            #pragma unroll
            for (int j = 0; j < 4; j++) h[j] = __floats2half2_rn(f[2*j], f[2*j+1]);
            *(uint4*)(orow + c0) = *(uint4*)h;
        }
    }
}

// ---------------- FA2-style flash attention (raw mma, register-resident) ------
#define FSMEM 55296

__global__ void __launch_bounds__(256, 2) flash_k(const __half* __restrict__ qkv,
                                                  __half* __restrict__ ctx) {
    extern __shared__ __align__(16) char sm[];
    __half* sQ = (__half*)sm;
    uint32_t sbase = (uint32_t)__cvta_generic_to_shared(sm);

    const int tid = threadIdx.x, lane = tid & 31, wid = tid >> 5;
    const int qt = blockIdx.x, z = blockIdx.y;
    const int b = z / NHz, h = z % NHz;

    const __half* Qp = qkv + (size_t)(b * Sz) * QLD + h * DHz;
    const __half* Kp = Qp + 768;
    const __half* Vp = Qp + 1536;

    #pragma unroll
    for (int s = 0; s < 4; s++) {
        int ch = tid + s * 256;
        int r = ch >> 3, c = (ch & 7) << 3;
        *(uint4*)(sQ + r * 72 + c) = *(const uint4*)(Qp + (size_t)(qt * 128 + r) * QLD + c);
    }

    auto issueKV = [&](int kt) {
        int st = kt & 1;
        uint32_t kb = sbase + 18432 + st * 18432;
        uint32_t vb = kb + 9216;
        #pragma unroll
        for (int i = 0; i < 2; i++) {
            int g = tid + i * 256;
            int r = g >> 3, c = g & 7;
            size_t go = (size_t)(kt * 64 + r) * QLD + c * 8;
            cpa16(kb + r * 144 + c * 16, Kp + go);
            cpa16(vb + r * 144 + c * 16, Vp + go);
        }
    };

    issueKV(0); cpa_commit();
    __syncthreads();

    const int m8 = lane & 7;
    const int g1 = ((lane >> 3) & 1) * 8;
    const int g2 = (lane >> 4) * 8;

    uint32_t qf[4][4];
    {
        const __half2 sc = __half2half2(__float2half_rn(0.125f));
        #pragma unroll
        for (int t = 0; t < 4; t++) {
            ldsm4(qf[t], sbase + (wid * 16 + g1 + m8) * 144 + (t * 16 + g2) * 2);
            #pragma unroll
            for (int j = 0; j < 4; j++) {
                __half2 v = __hmul2(*(__half2*)&qf[t][j], sc);
                qf[t][j] = *(uint32_t*)&v;
            }
        }
    }

    float oacc[8][4];
    #pragma unroll
    for (int j = 0; j < 8; j++) {
        oacc[j][0] = 0.0f; oacc[j][1] = 0.0f; oacc[j][2] = 0.0f; oacc[j][3] = 0.0f;
    }
    float mr0 = -1e30f, mr1 = -1e30f, lr0 = 0.0f, lr1 = 0.0f;

    for (int kt = 0; kt < 8; kt++) {
        cpa_wait<0>();
        __syncthreads();
        if (kt < 7) { issueKV(kt + 1); cpa_commit(); }
        const uint32_t kb = sbase + 18432 + (kt & 1) * 18432;
        const uint32_t vb = kb + 9216;

        float sacc[8][4];
        #pragma unroll
        for (int j = 0; j < 8; j++) {
            sacc[j][0] = 0.0f; sacc[j][1] = 0.0f; sacc[j][2] = 0.0f; sacc[j][3] = 0.0f;
        }
        #pragma unroll
        for (int t = 0; t < 4; t++) {
            #pragma unroll
            for (int u = 0; u < 4; u++) {
                uint32_t kf[4];
                ldsm4(kf, kb + (u * 16 + g2 + m8) * 144 + (t * 16 + g1) * 2);
                mma16816(sacc[2*u],     qf[t], kf[0], kf[1]);
                mma16816(sacc[2*u + 1], qf[t], kf[2], kf[3]);
            }
        }

        float mx0 = -1e30f, mx1 = -1e30f;
        #pragma unroll
        for (int j = 0; j < 8; j++) {
            mx0 = fmaxf(mx0, fmaxf(sacc[j][0], sacc[j][1]));
            mx1 = fmaxf(mx1, fmaxf(sacc[j][2], sacc[j][3]));
        }
        mx0 = fmaxf(mx0, __shfl_xor_sync(0xFFFFFFFFu, mx0, 1));
        mx0 = fmaxf(mx0, __shfl_xor_sync(0xFFFFFFFFu, mx0, 2));
        mx1 = fmaxf(mx1, __shfl_xor_sync(0xFFFFFFFFu, mx1, 1));
        mx1 = fmaxf(mx1, __shfl_xor_sync(0xFFFFFFFFu, mx1, 2));
        float mn0 = fmaxf(mr0, mx0), mn1 = fmaxf(mr1, mx1);
        float s0 = 0.0f, s1 = 0.0f;
        #pragma unroll
        for (int j = 0; j < 8; j++) {
            sacc[j][0] = __expf(sacc[j][0] - mn0);
            sacc[j][1] = __expf(sacc[j][1] - mn0);
            sacc[j][2] = __expf(sacc[j][2] - mn1);
            sacc[j][3] = __expf(sacc[j][3] - mn1);
            s0 += sacc[j][0] + sacc[j][1];
            s1 += sacc[j][2] + sacc[j][3];
        }
        s0 += __shfl_xor_sync(0xFFFFFFFFu, s0, 1);
        s0 += __shfl_xor_sync(0xFFFFFFFFu, s0, 2);
        s1 += __shfl_xor_sync(0xFFFFFFFFu, s1, 1);
        s1 += __shfl_xor_sync(0xFFFFFFFFu, s1, 2);
        float f0 = __expf(mr0 - mn0), f1 = __expf(mr1 - mn1);
        lr0 = lr0 * f0 + s0; lr1 = lr1 * f1 + s1;
        mr0 = mn0; mr1 = mn1;
        #pragma unroll
        for (int j = 0; j < 8; j++) {
            oacc[j][0] *= f0; oacc[j][1] *= f0;
            oacc[j][2] *= f1; oacc[j][3] *= f1;
        }

        #pragma unroll
        for (int t = 0; t < 4; t++) {
            uint32_t af[4];
            {
                __half2 a0 = __floats2half2_rn(sacc[2*t][0],     sacc[2*t][1]);
                __half2 a1 = __floats2half2_rn(sacc[2*t][2],     sacc[2*t][3]);
                __half2 a2 = __floats2half2_rn(sacc[2*t + 1][0], sacc[2*t + 1][1]);
                __half2 a3 = __floats2half2_rn(sacc[2*t + 1][2], sacc[2*t + 1][3]);
                af[0] = *(uint32_t*)&a0; af[1] = *(uint32_t*)&a1;
                af[2] = *(uint32_t*)&a2; af[3] = *(uint32_t*)&a3;
            }
            #pragma unroll
            for (int u = 0; u < 4; u++) {
                uint32_t vf[4];
                ldsm4t(vf, vb + (t * 16 + g1 + m8) * 144 + (u * 16 + g2) * 2);
                mma16816(oacc[2*u],     af, vf[0], vf[1]);
                mma16816(oacc[2*u + 1], af, vf[2], vf[3]);
            }
        }
    }

    float inv0 = 1.0f / lr0, inv1 = 1.0f / lr1;
    int row0 = qt * 128 + wid * 16 + (lane >> 2);
    __half* dst0 = ctx + ((size_t)(b * Sz) + row0) * Hz + h * DHz + (lane & 3) * 2;
    __half* dst1 = dst0 + 8 * Hz;
    #pragma unroll
    for (int j = 0; j < 8; j++) {
        __half2 o0 = __floats2half2_rn(oacc[j][0] * inv0, oacc[j][1] * inv0);
        __half2 o1 = __floats2half2_rn(oacc[j][2] * inv1, oacc[j][3] * inv1);
        *(__half2*)(dst0 + j * 8) = o0;
        *(__half2*)(dst1 + j * 8) = o1;
    }
}

// ---------------- host orchestration ----------------------------------------
extern "C" void kernel_launch(void* const* d_in, const int* in_sizes, int n_in,
                              void* d_out, int out_size) {
    const int*   ids   = (const int*)d_in[0];
    const float* word  = (const float*)d_in[1];
    const float* pos   = (const float*)d_in[2];
    const float* type0 = (const float*)d_in[3];
    const float* lneg  = (const float*)d_in[4];
    const float* lneb  = (const float*)d_in[5];
    const float* Wq    = (const float*)d_in[6];
    const float* bq    = (const float*)d_in[7];
    const float* Wk    = (const float*)d_in[8];
    const float* bk    = (const float*)d_in[9];
    const float* Wv    = (const float*)d_in[10];
    const float* bv    = (const float*)d_in[11];
    const float* Wo    = (const float*)d_in[12];
    const float* bo    = (const float*)d_in[13];
    const float* ln1g  = (const float*)d_in[14];
    const float* ln1b  = (const float*)d_in[15];
    const float* Wi    = (const float*)d_in[16];
    const float* bi    = (const float*)d_in[17];
    const float* Wo2   = (const float*)d_in[18];
    const float* bo2   = (const float*)d_in[19];
    const float* ln2g  = (const float*)d_in[20];
    const float* ln2b  = (const float*)d_in[21];

    float *x, *attn, *tmp, *tmp2, *tmp3;
    __half *xb, *attnb, *qkv, *ctx, *hh, *wqkvT, *woT, *wiT, *wo2T;
    cudaGetSymbolAddress((void**)&x,     g_x);
    cudaGetSymbolAddress((void**)&attn,  g_attn);
    cudaGetSymbolAddress((void**)&tmp,   g_tmp);
    cudaGetSymbolAddress((void**)&tmp2,  g_tmp2);
    cudaGetSymbolAddress((void**)&tmp3,  g_tmp3);
    cudaGetSymbolAddress((void**)&xb,    g_xb);
    cudaGetSymbolAddress((void**)&attnb, g_attnb);
    cudaGetSymbolAddress((void**)&qkv,   g_qkv);
    cudaGetSymbolAddress((void**)&ctx,   g_ctx);
    cudaGetSymbolAddress((void**)&hh,    g_h);
    cudaGetSymbolAddress((void**)&wqkvT, g_wqkvT);
    cudaGetSymbolAddress((void**)&woT,   g_woT);
    cudaGetSymbolAddress((void**)&wiT,   g_wiT);
    cudaGetSymbolAddress((void**)&wo2T,  g_wo2T);

    cudaFuncSetAttribute(hgemm_k<0>, cudaFuncAttributeMaxDynamicSharedMemorySize, GSMEM);
    cudaFuncSetAttribute(hgemm_k<3>, cudaFuncAttributeMaxDynamicSharedMemorySize, GSMEM);
    cudaFuncSetAttribute(hgemm64_k,  cudaFuncAttributeMaxDynamicSharedMemorySize, G64SMEM);
    cudaFuncSetAttribute(flash_k,    cudaFuncAttributeMaxDynamicSharedMemorySize, FSMEM);

    dim3 tb(32, 8);
    transpose_qkv_k<<<dim3(24, 24, 3 * Lz), tb>>>(Wq, Wk, Wv, wqkvT);
    transpose_f2h_k<<<dim3(24, 24, Lz), tb>>>(Wo, woT, Hz, Hz);
    transpose_f2h_k<<<dim3(96, 24, Lz), tb>>>(Wi, wiT, Hz, Iz);
    transpose_f2h_k<<<dim3(24, 96, Lz), tb>>>(Wo2, wo2T, Iz, Hz);
    embed_ln_k<<<Bz * Sz, 256>>>(ids, word, pos, type0, lneg, lneb, x, xb);

    const int M = Bz * Sz; // 8192
    for (int l = 0; l < Lz; l++) {
        // fused QKV projection
        {
            GP p{};
            p.A = xb;
            p.Bt = wqkvT + (size_t)l * 3 * Hz * Hz;
            p.bias = bq + l * Hz; p.bias1 = bk + l * Hz; p.bias2 = bv + l * Hz;
            p.outB = qkv; p.K = Hz; p.lda = Hz; p.ldo = QLD;
            hgemm_k<0><<<dim3(QLD / 128, M / 128, 1), 128, GSMEM>>>(p);
        }
        flash_k<<<dim3(Sz / 128, Bz * NHz), 256, FSMEM>>>(qkv, ctx);
        // O projection, split-K=2; zi==0 accumulator initialized from residual x
        {
            GP p{};
            p.A = ctx; p.Bt = woT + (size_t)l * Hz * Hz;
            p.res = x;
            p.outF = tmp; p.outF2 = tmp2;
            p.K = Hz / 2; p.lda = Hz; p.ldo = Hz;
            hgemm_k<3><<<dim3(Hz / 128, M / 128, 2), 128, GSMEM>>>(p);
        }
        // reduce(2) + bias + LN1 -> attn (fp32) + attnb (fp16)
        lnr_k<<<Bz * Sz, 256>>>(tmp, tmp2, nullptr, bo + l * Hz,
                                ln1g + l * Hz, ln1b + l * Hz, attn, attnb);
        // FFN1 + GELU (64-row tiles, occ 3, wave-efficient)
        {
            GP p{};
            p.A = attnb; p.Bt = wiT + (size_t)l * Hz * Iz;
            p.bias = bi + l * Iz; p.outB = hh;
            p.K = Hz; p.lda = Hz; p.ldo = Iz;
            hgemm64_k<<<dim3(Iz / 128, M / 64), 128, G64SMEM>>>(p);
        }
        // FFN2, split-K=3; zi==0 accumulator initialized from residual attn
        {
            GP p{};
            p.A = hh; p.Bt = wo2T + (size_t)l * Hz * Iz;
            p.res = attn;
            p.outF = tmp; p.outF2 = tmp2; p.outF3 = tmp3;
            p.K = Iz / 3; p.lda = Iz; p.ldo = Hz;
            hgemm_k<3><<<dim3(Hz / 128, M / 128, 3), 128, GSMEM>>>(p);
        }
        float* outp = (l == Lz - 1) ? (float*)d_out : x;
        // reduce(3) + bias + LN2 -> x (fp32) + xb (fp16)
        lnr_k<<<Bz * Sz, 256>>>(tmp, tmp2, tmp3, bo2 + l * Hz,
                                ln2g + l * Hz, ln2b + l * Hz, outp, xb);
    }
}

// round 16
// speedup vs baseline: 1.0057x; 1.0057x over previous
#include <cuda_runtime.h>
#include <cuda_fp16.h>
#include <mma.h>
#include <cstdint>
#include <cstddef>

using namespace nvcuda;

#define Bz 16
#define Sz 512
#define Hz 768
#define Lz 12
#define NHz 12
#define Iz 3072
#define DHz 64
#define BSHz (Bz*Sz*Hz)
#define QLD 2304

// ---------------- scratch (device globals; no allocations allowed) ----------
__device__ __align__(16) float  g_x[BSHz];        // fp32 residual master (attn input)
__device__ __align__(16) float  g_attn[BSHz];     // fp32 residual master (FFN input)
__device__ __align__(16) float  g_tmp[BSHz];      // split-K partial 0
__device__ __align__(16) float  g_tmp2[BSHz];     // split-K partial 1
__device__ __align__(16) float  g_tmp3[BSHz];     // split-K partial 2 (FFN2 split-3)
__device__ __align__(16) __half g_xb[BSHz];
__device__ __align__(16) __half g_attnb[BSHz];
__device__ __align__(16) __half g_qkv[3*BSHz];            // [8192][2304]
__device__ __align__(16) __half g_ctx[BSHz];
__device__ __align__(16) __half g_h[(size_t)Bz*Sz*Iz];
__device__ __align__(16) __half g_wqkvT[(size_t)Lz*3*Hz*Hz];   // [L][2304][768]
__device__ __align__(16) __half g_woT[(size_t)Lz*Hz*Hz];       // [L][768][768]
__device__ __align__(16) __half g_wiT[(size_t)Lz*Hz*Iz];       // [L][3072][768]
__device__ __align__(16) __half g_wo2T[(size_t)Lz*Hz*Iz];      // [L][768][3072]

// ---------------- cp.async helpers ------------------------------------------
__device__ __forceinline__ void cpa16(uint32_t d, const void* s) {
    asm volatile("cp.async.cg.shared.global [%0], [%1], 16;" :: "r"(d), "l"(s));
}
__device__ __forceinline__ void cpa_commit() { asm volatile("cp.async.commit_group;"); }
template<int N> __device__ __forceinline__ void cpa_wait() {
    asm volatile("cp.async.wait_group %0;" :: "n"(N));
}

// ---------------- mma / ldmatrix helpers -------------------------------------
__device__ __forceinline__ void ldsm4(uint32_t* r, uint32_t a) {
    asm volatile("ldmatrix.sync.aligned.m8n8.x4.shared.b16 {%0,%1,%2,%3}, [%4];"
        : "=r"(r[0]), "=r"(r[1]), "=r"(r[2]), "=r"(r[3]) : "r"(a));
}
__device__ __forceinline__ void ldsm4t(uint32_t* r, uint32_t a) {
    asm volatile("ldmatrix.sync.aligned.m8n8.x4.trans.shared.b16 {%0,%1,%2,%3}, [%4];"
        : "=r"(r[0]), "=r"(r[1]), "=r"(r[2]), "=r"(r[3]) : "r"(a));
}
__device__ __forceinline__ void mma16816(float* c, const uint32_t* a, uint32_t b0, uint32_t b1) {
    asm volatile("mma.sync.aligned.m16n8k16.row.col.f32.f16.f16.f32 "
        "{%0,%1,%2,%3}, {%4,%5,%6,%7}, {%8,%9}, {%0,%1,%2,%3};"
        : "+f"(c[0]), "+f"(c[1]), "+f"(c[2]), "+f"(c[3])
        : "r"(a[0]), "r"(a[1]), "r"(a[2]), "r"(a[3]), "r"(b0), "r"(b1));
}

// ---------------- weight transpose + fp32->fp16 (vectorized writes) ----------
// src [R,C] fp32 (slice z) -> dst [C,R] fp16. Tile: 32 cols x 64 rows.
// Writes: each thread packs 8 halves -> one 16B-aligned uint4 (full 128B/warp).
__global__ void transpose_f2h_k(const float* __restrict__ src, __half* __restrict__ dst,
                                int R, int C) {
    __shared__ float t[64][33];
    const int bx = blockIdx.x * 32, by = blockIdx.y * 64;
    const float* s = src + (size_t)blockIdx.z * R * C;
    __half* d = dst + (size_t)blockIdx.z * R * C;
    const int tx = threadIdx.x & 31;
    const int ty = threadIdx.x >> 5;     // 0..7
    #pragma unroll
    for (int i = 0; i < 8; i++)
        t[ty + i * 8][tx] = s[(size_t)(by + ty + i * 8) * C + bx + tx];
    __syncthreads();
    const int c  = threadIdx.x >> 3;       // 0..31
    const int r0 = (threadIdx.x & 7) * 8;  // 0..56
    __half2 h[4];
    #pragma unroll
    for (int k = 0; k < 4; k++)
        h[k] = __floats2half2_rn(t[r0 + 2 * k][c], t[r0 + 2 * k + 1][c]);
    *(uint4*)(d + (size_t)(bx + c) * R + by + r0) = *(uint4*)h;
}

// QKV: 3 sources -> [L][2304][768] fp16 (each slot transposed), same scheme
__global__ void transpose_qkv_k(const float* __restrict__ q, const float* __restrict__ k,
                                const float* __restrict__ v, __half* __restrict__ dst) {
    __shared__ float t[64][33];
    const int z = blockIdx.z;
    const int slot = z / Lz, l = z % Lz;
    const float* s = (slot == 0 ? q : (slot == 1 ? k : v)) + (size_t)l * Hz * Hz;
    __half* d = dst + ((size_t)l * 3 + slot) * Hz * Hz;
    const int bx = blockIdx.x * 32, by = blockIdx.y * 64;
    const int tx = threadIdx.x & 31;
    const int ty = threadIdx.x >> 5;
    #pragma unroll
    for (int i = 0; i < 8; i++)
        t[ty + i * 8][tx] = s[(size_t)(by + ty + i * 8) * Hz + bx + tx];
    __syncthreads();
    const int c  = threadIdx.x >> 3;
    const int r0 = (threadIdx.x & 7) * 8;
    __half2 h[4];
    #pragma unroll
    for (int kk = 0; kk < 4; kk++)
        h[kk] = __floats2half2_rn(t[r0 + 2 * kk][c], t[r0 + 2 * kk + 1][c]);
    *(uint4*)(d + (size_t)(bx + c) * Hz + by + r0) = *(uint4*)h;
}

// ---------------- block reductions ------------------------------------------
__device__ __forceinline__ float bsum256(float v, float* sm) {
    #pragma unroll
    for (int o = 16; o; o >>= 1) v += __shfl_xor_sync(0xFFFFFFFFu, v, o);
    int t = threadIdx.x;
    if ((t & 31) == 0) sm[t >> 5] = v;
    __syncthreads();
    float r = sm[0];
    #pragma unroll
    for (int i = 1; i < 8; i++) r += sm[i];
    __syncthreads();
    return r;
}

// ---------------- embedding + LN ---------------------------------------------
__global__ void embed_ln_k(const int* __restrict__ ids,
                           const float* __restrict__ we,
                           const float* __restrict__ pe,
                           const float* __restrict__ te,
                           const float* __restrict__ g,
                           const float* __restrict__ b,
                           float* __restrict__ dF,
                           __half* __restrict__ dB) {
    __shared__ float sm[8];
    int row = blockIdx.x;
    int s_ = row & (Sz - 1);
    int id = ids[row];
    int t = threadIdx.x;
    float v[3];
    #pragma unroll
    for (int i = 0; i < 3; i++) {
        int col = t + i * 256;
        v[i] = we[(size_t)id * Hz + col] + pe[(size_t)(s_ + 2) * Hz + col] + te[col];
    }
    float mean = bsum256(v[0] + v[1] + v[2], sm) * (1.0f / Hz);
    float d0 = v[0] - mean, d1 = v[1] - mean, d2 = v[2] - mean;
    float var = bsum256(d0*d0 + d1*d1 + d2*d2, sm) * (1.0f / Hz);
    float rs = rsqrtf(var + 1e-5f);
    size_t base = (size_t)row * Hz;
    #pragma unroll
    for (int i = 0; i < 3; i++) {
        int col = t + i * 256;
        float y = (v[i] - mean) * rs * g[col] + b[col];
        dF[base + col] = y;
        dB[base + col] = __float2half_rn(y);
    }
}

// ---------------- fused split-K reduce + bias + fp32 residual + LayerNorm ----
// p2 may be null (2-way split).
__global__ void lnr_k(const float* __restrict__ p0,
                      const float* __restrict__ p1,
                      const float* __restrict__ p2,
                      const float* __restrict__ bias,
                      const float* __restrict__ res,
                      const float* __restrict__ g,
                      const float* __restrict__ b,
                      float* __restrict__ dF,
                      __half* __restrict__ dB) {
    __shared__ float sm[8];
    size_t base = (size_t)blockIdx.x * Hz;
    int t = threadIdx.x;
    float v[3];
    #pragma unroll
    for (int i = 0; i < 3; i++) {
        int col = t + i * 256;
        float s = p0[base + col] + p1[base + col];
        if (p2) s += p2[base + col];
        v[i] = s + bias[col] + res[base + col];
    }
    float mean = bsum256(v[0] + v[1] + v[2], sm) * (1.0f / Hz);
    float d0 = v[0] - mean, d1 = v[1] - mean, d2 = v[2] - mean;
    float var = bsum256(d0*d0 + d1*d1 + d2*d2, sm) * (1.0f / Hz);
    float rs = rsqrtf(var + 1e-5f);
    #pragma unroll
    for (int i = 0; i < 3; i++) {
        int col = t + i * 256;
        float y = (v[i] - mean) * rs * g[col] + b[col];
        dF[base + col] = y;
        dB[base + col] = __float2half_rn(y);
    }
}

// ---------------- HMMA GEMM: 128x128 tile, 4 warps of 64x64, BK=64, 3-stage --
// A [M, lda] fp16, uses cols [z*K, z*K+K). Bt [N, lda] same. grid (N/128, M/128, splits).
// EPI: 0 outB = half(acc + bias)   (bias1/bias2: QKV slot biases by column)
//      3 raw fp32 acc -> outF[zi], direct fragment stores (R9-proven path)
struct GP {
    const __half* A;
    const __half* Bt;
    const float* bias;
    const float* bias1;
    const float* bias2;
    float* outF;
    float* outF2;
    float* outF3;
    __half* outB;
    int K, lda, ldo;
};

#define GSMEM 110592

template<int EPI>
__global__ void __launch_bounds__(128, 2) hgemm_k(GP p) {
    extern __shared__ __align__(16) char smraw[];
    const int tid = threadIdx.x;
    const int wid = tid >> 5;
    const int wm = wid >> 1, wn = wid & 1;     // 2x2 warp grid, 64x64 each
    const int m0 = blockIdx.y * 128, n0 = blockIdx.x * 128;
    const int zi = blockIdx.z;

    const __half* Arow = p.A + (size_t)m0 * p.lda + (size_t)zi * p.K;
    const __half* Brow = p.Bt + (size_t)n0 * p.lda + (size_t)zi * p.K;
    const int K = p.K, KT = K >> 6, lda = p.lda;

    uint32_t sbase = (uint32_t)__cvta_generic_to_shared(smraw);

    auto issue = [&](int kt, int st) {
        const __half* as = Arow + kt * 64;
        const __half* bs = Brow + kt * 64;
        const uint32_t sa = sbase + st * 36864;
        const uint32_t sb = sa + 18432;
        #pragma unroll
        for (int i = 0; i < 8; i++) {
            int g = tid + i * 128;
            int r = g >> 3, c = g & 7;
            cpa16(sa + r * 144 + c * 16, as + (size_t)r * lda + c * 8);
            cpa16(sb + r * 144 + c * 16, bs + (size_t)r * lda + c * 8);
        }
    };

    issue(0, 0); cpa_commit();
    issue(1, 1); cpa_commit();

    wmma::fragment<wmma::accumulator, 16, 16, 16, float> acc[4][4];
    #pragma unroll
    for (int i = 0; i < 4; i++)
        #pragma unroll
        for (int j = 0; j < 4; j++) wmma::fill_fragment(acc[i][j], 0.0f);

    for (int kt = 0; kt < KT; kt++) {
        cpa_wait<1>();
        __syncthreads();
        if (kt + 2 < KT) issue(kt + 2, (kt + 2) % 3);
        cpa_commit();

        const int st = kt % 3;
        const __half* sA = (const __half*)(smraw + st * 36864);
        const __half* sB = sA + 9216;
        #pragma unroll
        for (int kk = 0; kk < 4; kk++) {
            wmma::fragment<wmma::matrix_a, 16, 16, 16, __half, wmma::row_major> af[4];
            #pragma unroll
            for (int i = 0; i < 4; i++)
                wmma::load_matrix_sync(af[i], sA + (wm * 64 + i * 16) * 72 + kk * 16, 72);
            wmma::fragment<wmma::matrix_b, 16, 16, 16, __half, wmma::col_major> bf[4];
            #pragma unroll
            for (int j = 0; j < 4; j++)
                wmma::load_matrix_sync(bf[j], sB + (wn * 64 + j * 16) * 72 + kk * 16, 72);
            #pragma unroll
            for (int i = 0; i < 4; i++)
                #pragma unroll
                for (int j = 0; j < 4; j++)
                    wmma::mma_sync(acc[i][j], af[i], bf[j], acc[i][j]);
        }
    }

    if (EPI == 3) {
        float* outp = (zi == 0) ? p.outF : ((zi == 1) ? p.outF2 : p.outF3);
        float* out = outp + (size_t)m0 * p.ldo + n0;
        #pragma unroll
        for (int i = 0; i < 4; i++)
            #pragma unroll
            for (int j = 0; j < 4; j++)
                wmma::store_matrix_sync(out + (size_t)(wm * 64 + i * 16) * p.ldo + wn * 64 + j * 16,
                                        acc[i][j], p.ldo, wmma::mem_row_major);
        return;
    }

    __syncthreads();
    float* epi = (float*)smraw;
    #pragma unroll
    for (int i = 0; i < 4; i++)
        #pragma unroll
        for (int j = 0; j < 4; j++)
            wmma::store_matrix_sync(epi + (wm * 64 + i * 16) * 132 + wn * 64 + j * 16,
                                    acc[i][j], 132, wmma::mem_row_major);
    __syncthreads();

    {
        const float* ep = epi + tid * 132;
        const int gm = m0 + tid;
        __half* orow = p.outB + (size_t)gm * p.ldo + n0;
        #pragma unroll 4
        for (int c0 = 0; c0 < 128; c0 += 8) {
            float f[8];
            #pragma unroll
            for (int j = 0; j < 8; j++) {
                int n = n0 + c0 + j;
                float bv;
                if (EPI == 0 && p.bias1) {
                    const float* bp = n < 768 ? p.bias : (n < 1536 ? p.bias1 : p.bias2);
                    bv = bp[n & 767];
                } else {
                    bv = p.bias[n];
                }
                f[j] = ep[c0 + j] + bv;
            }
            __half2 h[4];
            #pragma unroll
            for (int j = 0; j < 4; j++) h[j] = __floats2half2_rn(f[2*j], f[2*j+1]);
            *(uint4*)(orow + c0) = *(uint4*)h;
        }
    }
}

// ---------------- FFN1 GEMM: 64x128 tile, 4 warps of 32x64, BK=64, 2-stage ---
// occupancy 3 -> 444 blocks/wave; 3072 blocks = 6.92->7 waves (98.8% wave eff).
// outB = half(gelu(acc + bias))
#define G64SMEM 55296

__global__ void __launch_bounds__(128, 3) hgemm64_k(GP p) {
    extern __shared__ __align__(16) char smraw[];
    const int tid = threadIdx.x;
    const int wid = tid >> 5;
    const int wm = wid >> 1, wn = wid & 1;     // 2x2 warp grid, 32x64 each
    const int m0 = blockIdx.y * 64, n0 = blockIdx.x * 128;

    const __half* Arow = p.A + (size_t)m0 * p.lda;
    const __half* Brow = p.Bt + (size_t)n0 * p.lda;
    const int K = p.K, KT = K >> 6, lda = p.lda;

    uint32_t sbase = (uint32_t)__cvta_generic_to_shared(smraw);

    auto issue = [&](int kt, int st) {
        const __half* as = Arow + kt * 64;
        const __half* bs = Brow + kt * 64;
        const uint32_t sa = sbase + st * 27648;
        const uint32_t sb = sa + 9216;
        #pragma unroll
        for (int i = 0; i < 4; i++) {
            int g = tid + i * 128;
            int r = g >> 3, c = g & 7;
            cpa16(sa + r * 144 + c * 16, as + (size_t)r * lda + c * 8);
        }
        #pragma unroll
        for (int i = 0; i < 8; i++) {
            int g = tid + i * 128;
            int r = g >> 3, c = g & 7;
            cpa16(sb + r * 144 + c * 16, bs + (size_t)r * lda + c * 8);
        }
    };

    issue(0, 0); cpa_commit();

    wmma::fragment<wmma::accumulator, 16, 16, 16, float> acc[2][4];
    #pragma unroll
    for (int i = 0; i < 2; i++)
        #pragma unroll
        for (int j = 0; j < 4; j++) wmma::fill_fragment(acc[i][j], 0.0f);

    for (int kt = 0; kt < KT; kt++) {
        cpa_wait<0>();
        __syncthreads();
        if (kt + 1 < KT) { issue(kt + 1, (kt + 1) & 1); cpa_commit(); }

        const int st = kt & 1;
        const __half* sA = (const __half*)(smraw + st * 27648);
        const __half* sB = sA + 4608;
        #pragma unroll
        for (int kk = 0; kk < 4; kk++) {
            wmma::fragment<wmma::matrix_a, 16, 16, 16, __half, wmma::row_major> af[2];
            #pragma unroll
            for (int i = 0; i < 2; i++)
                wmma::load_matrix_sync(af[i], sA + (wm * 32 + i * 16) * 72 + kk * 16, 72);
            wmma::fragment<wmma::matrix_b, 16, 16, 16, __half, wmma::col_major> bf[4];
            #pragma unroll
            for (int j = 0; j < 4; j++)
                wmma::load_matrix_sync(bf[j], sB + (wn * 64 + j * 16) * 72 + kk * 16, 72);
            #pragma unroll
            for (int i = 0; i < 2; i++)
                #pragma unroll
                for (int j = 0; j < 4; j++)
                    wmma::mma_sync(acc[i][j], af[i], bf[j], acc[i][j]);
        }
        __syncthreads();
    }

    float* epi = (float*)smraw;
    #pragma unroll
    for (int i = 0; i < 2; i++)
        #pragma unroll
        for (int j = 0; j < 4; j++)
            wmma::store_matrix_sync(epi + (wm * 32 + i * 16) * 132 + wn * 64 + j * 16,
                                    acc[i][j], 132, wmma::mem_row_major);
    __syncthreads();

    {
        const int r = tid >> 1;
        const int co = (tid & 1) * 64;
        const float* ep = epi + r * 132 + co;
        const int gm = m0 + r;
        const int gn0 = n0 + co;
        __half* orow = p.outB + (size_t)gm * p.ldo + gn0;
        #pragma unroll 4
        for (int c0 = 0; c0 < 64; c0 += 8) {
            float f[8];
            #pragma unroll
            for (int j = 0; j < 8; j++) f[j] = ep[c0 + j] + p.bias[gn0 + c0 + j];
            #pragma unroll
            for (int j = 0; j < 8; j++)
                f[j] = 0.5f * f[j] * (1.0f + erff(f[j] * 0.70710678118654752f));
            __half2 h[4];
            #pragma unroll
            for (int j = 0; j < 4; j++) h[j] = __floats2half2_rn(f[2*j], f[2*j+1]);
            *(uint4*)(orow + c0) = *(uint4*)h;
        }
    }
}

// ---------------- FA2-style flash attention (raw mma, register-resident) ------
#define FSMEM 55296

__global__ void __launch_bounds__(256, 2) flash_k(const __half* __restrict__ qkv,
                                                  __half* __restrict__ ctx) {
    extern __shared__ __align__(16) char sm[];
    __half* sQ = (__half*)sm;
    uint32_t sbase = (uint32_t)__cvta_generic_to_shared(sm);

    const int tid = threadIdx.x, lane = tid & 31, wid = tid >> 5;
    const int qt = blockIdx.x, z = blockIdx.y;
    const int b = z / NHz, h = z % NHz;

    const __half* Qp = qkv + (size_t)(b * Sz) * QLD + h * DHz;
    const __half* Kp = Qp + 768;
    const __half* Vp = Qp + 1536;

    #pragma unroll
    for (int s = 0; s < 4; s++) {
        int ch = tid + s * 256;
        int r = ch >> 3, c = (ch & 7) << 3;
        *(uint4*)(sQ + r * 72 + c) = *(const uint4*)(Qp + (size_t)(qt * 128 + r) * QLD + c);
    }

    auto issueKV = [&](int kt) {
        int st = kt & 1;
        uint32_t kb = sbase + 18432 + st * 18432;
        uint32_t vb = kb + 9216;
        #pragma unroll
        for (int i = 0; i < 2; i++) {
            int g = tid + i * 256;
            int r = g >> 3, c = g & 7;
            size_t go = (size_t)(kt * 64 + r) * QLD + c * 8;
            cpa16(kb + r * 144 + c * 16, Kp + go);
            cpa16(vb + r * 144 + c * 16, Vp + go);
        }
    };

    issueKV(0); cpa_commit();
    __syncthreads();

    const int m8 = lane & 7;
    const int g1 = ((lane >> 3) & 1) * 8;
    const int g2 = (lane >> 4) * 8;

    uint32_t qf[4][4];
    {
        const __half2 sc = __half2half2(__float2half_rn(0.125f));
        #pragma unroll
        for (int t = 0; t < 4; t++) {
            ldsm4(qf[t], sbase + (wid * 16 + g1 + m8) * 144 + (t * 16 + g2) * 2);
            #pragma unroll
            for (int j = 0; j < 4; j++) {
                __half2 v = __hmul2(*(__half2*)&qf[t][j], sc);
                qf[t][j] = *(uint32_t*)&v;
            }
        }
    }

    float oacc[8][4];
    #pragma unroll
    for (int j = 0; j < 8; j++) {
        oacc[j][0] = 0.0f; oacc[j][1] = 0.0f; oacc[j][2] = 0.0f; oacc[j][3] = 0.0f;
    }
    float mr0 = -1e30f, mr1 = -1e30f, lr0 = 0.0f, lr1 = 0.0f;

    for (int kt = 0; kt < 8; kt++) {
        cpa_wait<0>();
        __syncthreads();
        if (kt < 7) { issueKV(kt + 1); cpa_commit(); }
        const uint32_t kb = sbase + 18432 + (kt & 1) * 18432;
        const uint32_t vb = kb + 9216;

        float sacc[8][4];
        #pragma unroll
        for (int j = 0; j < 8; j++) {
            sacc[j][0] = 0.0f; sacc[j][1] = 0.0f; sacc[j][2] = 0.0f; sacc[j][3] = 0.0f;
        }
        #pragma unroll
        for (int t = 0; t < 4; t++) {
            #pragma unroll
            for (int u = 0; u < 4; u++) {
                uint32_t kf[4];
                ldsm4(kf, kb + (u * 16 + g2 + m8) * 144 + (t * 16 + g1) * 2);
                mma16816(sacc[2*u],     qf[t], kf[0], kf[1]);
                mma16816(sacc[2*u + 1], qf[t], kf[2], kf[3]);
            }
        }

        float mx0 = -1e30f, mx1 = -1e30f;
        #pragma unroll
        for (int j = 0; j < 8; j++) {
            mx0 = fmaxf(mx0, fmaxf(sacc[j][0], sacc[j][1]));
            mx1 = fmaxf(mx1, fmaxf(sacc[j][2], sacc[j][3]));
        }
        mx0 = fmaxf(mx0, __shfl_xor_sync(0xFFFFFFFFu, mx0, 1));
        mx0 = fmaxf(mx0, __shfl_xor_sync(0xFFFFFFFFu, mx0, 2));
        mx1 = fmaxf(mx1, __shfl_xor_sync(0xFFFFFFFFu, mx1, 1));
        mx1 = fmaxf(mx1, __shfl_xor_sync(0xFFFFFFFFu, mx1, 2));
        float mn0 = fmaxf(mr0, mx0), mn1 = fmaxf(mr1, mx1);
        float s0 = 0.0f, s1 = 0.0f;
        #pragma unroll
        for (int j = 0; j < 8; j++) {
            sacc[j][0] = __expf(sacc[j][0] - mn0);
            sacc[j][1] = __expf(sacc[j][1] - mn0);
            sacc[j][2] = __expf(sacc[j][2] - mn1);
            sacc[j][3] = __expf(sacc[j][3] - mn1);
            s0 += sacc[j][0] + sacc[j][1];
            s1 += sacc[j][2] + sacc[j][3];
        }
        s0 += __shfl_xor_sync(0xFFFFFFFFu, s0, 1);
        s0 += __shfl_xor_sync(0xFFFFFFFFu, s0, 2);
        s1 += __shfl_xor_sync(0xFFFFFFFFu, s1, 1);
        s1 += __shfl_xor_sync(0xFFFFFFFFu, s1, 2);
        float f0 = __expf(mr0 - mn0), f1 = __expf(mr1 - mn1);
        lr0 = lr0 * f0 + s0; lr1 = lr1 * f1 + s1;
        mr0 = mn0; mr1 = mn1;
        #pragma unroll
        for (int j = 0; j < 8; j++) {
            oacc[j][0] *= f0; oacc[j][1] *= f0;
            oacc[j][2] *= f1; oacc[j][3] *= f1;
        }

        #pragma unroll
        for (int t = 0; t < 4; t++) {
            uint32_t af[4];
            {
                __half2 a0 = __floats2half2_rn(sacc[2*t][0],     sacc[2*t][1]);
                __half2 a1 = __floats2half2_rn(sacc[2*t][2],     sacc[2*t][3]);
                __half2 a2 = __floats2half2_rn(sacc[2*t + 1][0], sacc[2*t + 1][1]);
                __half2 a3 = __floats2half2_rn(sacc[2*t + 1][2], sacc[2*t + 1][3]);
                af[0] = *(uint32_t*)&a0; af[1] = *(uint32_t*)&a1;
                af[2] = *(uint32_t*)&a2; af[3] = *(uint32_t*)&a3;
            }
            #pragma unroll
            for (int u = 0; u < 4; u++) {
                uint32_t vf[4];
                ldsm4t(vf, vb + (t * 16 + g1 + m8) * 144 + (u * 16 + g2) * 2);
                mma16816(oacc[2*u],     af, vf[0], vf[1]);
                mma16816(oacc[2*u + 1], af, vf[2], vf[3]);
            }
        }
    }

    float inv0 = 1.0f / lr0, inv1 = 1.0f / lr1;
    int row0 = qt * 128 + wid * 16 + (lane >> 2);
    __half* dst0 = ctx + ((size_t)(b * Sz) + row0) * Hz + h * DHz + (lane & 3) * 2;
    __half* dst1 = dst0 + 8 * Hz;
    #pragma unroll
    for (int j = 0; j < 8; j++) {
        __half2 o0 = __floats2half2_rn(oacc[j][0] * inv0, oacc[j][1] * inv0);
        __half2 o1 = __floats2half2_rn(oacc[j][2] * inv1, oacc[j][3] * inv1);
        *(__half2*)(dst0 + j * 8) = o0;
        *(__half2*)(dst1 + j * 8) = o1;
    }
}

// ---------------- host orchestration ----------------------------------------
extern "C" void kernel_launch(void* const* d_in, const int* in_sizes, int n_in,
                              void* d_out, int out_size) {
    const int*   ids   = (const int*)d_in[0];
    const float* word  = (const float*)d_in[1];
    const float* pos   = (const float*)d_in[2];
    const float* type0 = (const float*)d_in[3];
    const float* lneg  = (const float*)d_in[4];
    const float* lneb  = (const float*)d_in[5];
    const float* Wq    = (const float*)d_in[6];
    const float* bq    = (const float*)d_in[7];
    const float* Wk    = (const float*)d_in[8];
    const float* bk    = (const float*)d_in[9];
    const float* Wv    = (const float*)d_in[10];
    const float* bv    = (const float*)d_in[11];
    const float* Wo    = (const float*)d_in[12];
    const float* bo    = (const float*)d_in[13];
    const float* ln1g  = (const float*)d_in[14];
    const float* ln1b  = (const float*)d_in[15];
    const float* Wi    = (const float*)d_in[16];
    const float* bi    = (const float*)d_in[17];
    const float* Wo2   = (const float*)d_in[18];
    const float* bo2   = (const float*)d_in[19];
    const float* ln2g  = (const float*)d_in[20];
    const float* ln2b  = (const float*)d_in[21];

    float *x, *attn, *tmp, *tmp2, *tmp3;
    __half *xb, *attnb, *qkv, *ctx, *hh, *wqkvT, *woT, *wiT, *wo2T;
    cudaGetSymbolAddress((void**)&x,     g_x);
    cudaGetSymbolAddress((void**)&attn,  g_attn);
    cudaGetSymbolAddress((void**)&tmp,   g_tmp);
    cudaGetSymbolAddress((void**)&tmp2,  g_tmp2);
    cudaGetSymbolAddress((void**)&tmp3,  g_tmp3);
    cudaGetSymbolAddress((void**)&xb,    g_xb);
    cudaGetSymbolAddress((void**)&attnb, g_attnb);
    cudaGetSymbolAddress((void**)&qkv,   g_qkv);
    cudaGetSymbolAddress((void**)&ctx,   g_ctx);
    cudaGetSymbolAddress((void**)&hh,    g_h);
    cudaGetSymbolAddress((void**)&wqkvT, g_wqkvT);
    cudaGetSymbolAddress((void**)&woT,   g_woT);
    cudaGetSymbolAddress((void**)&wiT,   g_wiT);
    cudaGetSymbolAddress((void**)&wo2T,  g_wo2T);

    cudaFuncSetAttribute(hgemm_k<0>, cudaFuncAttributeMaxDynamicSharedMemorySize, GSMEM);
    cudaFuncSetAttribute(hgemm_k<3>, cudaFuncAttributeMaxDynamicSharedMemorySize, GSMEM);
    cudaFuncSetAttribute(hgemm64_k,  cudaFuncAttributeMaxDynamicSharedMemorySize, G64SMEM);
    cudaFuncSetAttribute(flash_k,    cudaFuncAttributeMaxDynamicSharedMemorySize, FSMEM);

    // transposes: tile = 32 cols x 64 rows, 256 threads flat
    transpose_qkv_k<<<dim3(Hz/32, Hz/64, 3 * Lz), 256>>>(Wq, Wk, Wv, wqkvT);
    transpose_f2h_k<<<dim3(Hz/32, Hz/64, Lz), 256>>>(Wo, woT, Hz, Hz);
    transpose_f2h_k<<<dim3(Iz/32, Hz/64, Lz), 256>>>(Wi, wiT, Hz, Iz);
    transpose_f2h_k<<<dim3(Hz/32, Iz/64, Lz), 256>>>(Wo2, wo2T, Iz, Hz);
    embed_ln_k<<<Bz * Sz, 256>>>(ids, word, pos, type0, lneg, lneb, x, xb);

    const int M = Bz * Sz; // 8192
    for (int l = 0; l < Lz; l++) {
        // fused QKV projection
        {
            GP p{};
            p.A = xb;
            p.Bt = wqkvT + (size_t)l * 3 * Hz * Hz;
            p.bias = bq + l * Hz; p.bias1 = bk + l * Hz; p.bias2 = bv + l * Hz;
            p.outB = qkv; p.K = Hz; p.lda = Hz; p.ldo = QLD;
            hgemm_k<0><<<dim3(QLD / 128, M / 128, 1), 128, GSMEM>>>(p);
        }
        flash_k<<<dim3(Sz / 128, Bz * NHz), 256, FSMEM>>>(qkv, ctx);
        // O projection, split-K=2, raw fp32 partials
        {
            GP p{};
            p.A = ctx; p.Bt = woT + (size_t)l * Hz * Hz;
            p.outF = tmp; p.outF2 = tmp2;
            p.K = Hz / 2; p.lda = Hz; p.ldo = Hz;
            hgemm_k<3><<<dim3(Hz / 128, M / 128, 2), 128, GSMEM>>>(p);
        }
        // reduce(2) + bias + fp32 residual(x) + LN1 -> attn (fp32) + attnb (fp16)
        lnr_k<<<Bz * Sz, 256>>>(tmp, tmp2, nullptr, bo + l * Hz, x,
                                ln1g + l * Hz, ln1b + l * Hz, attn, attnb);
        // FFN1 + GELU (64-row tiles, occ 3, wave-efficient)
        {
            GP p{};
            p.A = attnb; p.Bt = wiT + (size_t)l * Hz * Iz;
            p.bias = bi + l * Iz; p.outB = hh;
            p.K = Hz; p.lda = Hz; p.ldo = Iz;
            hgemm64_k<<<dim3(Iz / 128, M / 64), 128, G64SMEM>>>(p);
        }
        // FFN2, split-K=3, raw fp32 partials
        {
            GP p{};
            p.A = hh; p.Bt = wo2T + (size_t)l * Hz * Iz;
            p.outF = tmp; p.outF2 = tmp2; p.outF3 = tmp3;
            p.K = Iz / 3; p.lda = Iz; p.ldo = Hz;
            hgemm_k<3><<<dim3(Hz / 128, M / 128, 3), 128, GSMEM>>>(p);
        }
        float* outp = (l == Lz - 1) ? (float*)d_out : x;
        // reduce(3) + bias + fp32 residual(attn) + LN2 -> x (fp32) + xb (fp16)
        lnr_k<<<Bz * Sz, 256>>>(tmp, tmp2, tmp3, bo2 + l * Hz, attn,
                                ln2g + l * Hz, ln2b + l * Hz, outp, xb);
    }
}

// round 17
// speedup vs baseline: 1.0181x; 1.0123x over previous
#include <cuda_runtime.h>
#include <cuda_fp16.h>
#include <mma.h>
#include <cstdint>
#include <cstddef>

using namespace nvcuda;

#define Bz 16
#define Sz 512
#define Hz 768
#define Lz 12
#define NHz 12
#define Iz 3072
#define DHz 64
#define BSHz (Bz*Sz*Hz)
#define QLD 2304

// ---------------- scratch (device globals; no allocations allowed) ----------
__device__ __align__(16) float  g_x[BSHz];        // fp32 residual master (attn input)
__device__ __align__(16) float  g_attn[BSHz];     // fp32 residual master (FFN input)
__device__ __align__(16) float  g_tmp[BSHz];      // split-K partial 0
__device__ __align__(16) float  g_tmp2[BSHz];     // split-K partial 1
__device__ __align__(16) float  g_tmp3[BSHz];     // split-K partial 2 (FFN2 split-3)
__device__ __align__(16) __half g_xb[BSHz];
__device__ __align__(16) __half g_attnb[BSHz];
__device__ __align__(16) __half g_qkv[3*BSHz];            // [8192][2304]
__device__ __align__(16) __half g_ctx[BSHz];
__device__ __align__(16) __half g_h[(size_t)Bz*Sz*Iz];
__device__ __align__(16) __half g_wqkvT[(size_t)Lz*3*Hz*Hz];   // [L][2304][768]
__device__ __align__(16) __half g_woT[(size_t)Lz*Hz*Hz];       // [L][768][768]
__device__ __align__(16) __half g_wiT[(size_t)Lz*Hz*Iz];       // [L][3072][768]
__device__ __align__(16) __half g_wo2T[(size_t)Lz*Hz*Iz];      // [L][768][3072]

// ---------------- cp.async helpers ------------------------------------------
__device__ __forceinline__ void cpa16(uint32_t d, const void* s) {
    asm volatile("cp.async.cg.shared.global [%0], [%1], 16;" :: "r"(d), "l"(s));
}
__device__ __forceinline__ void cpa_commit() { asm volatile("cp.async.commit_group;"); }
template<int N> __device__ __forceinline__ void cpa_wait() {
    asm volatile("cp.async.wait_group %0;" :: "n"(N));
}

// ---------------- mma / ldmatrix helpers -------------------------------------
__device__ __forceinline__ void ldsm4(uint32_t* r, uint32_t a) {
    asm volatile("ldmatrix.sync.aligned.m8n8.x4.shared.b16 {%0,%1,%2,%3}, [%4];"
        : "=r"(r[0]), "=r"(r[1]), "=r"(r[2]), "=r"(r[3]) : "r"(a));
}
__device__ __forceinline__ void ldsm4t(uint32_t* r, uint32_t a) {
    asm volatile("ldmatrix.sync.aligned.m8n8.x4.trans.shared.b16 {%0,%1,%2,%3}, [%4];"
        : "=r"(r[0]), "=r"(r[1]), "=r"(r[2]), "=r"(r[3]) : "r"(a));
}
__device__ __forceinline__ void mma16816(float* c, const uint32_t* a, uint32_t b0, uint32_t b1) {
    asm volatile("mma.sync.aligned.m16n8k16.row.col.f32.f16.f16.f32 "
        "{%0,%1,%2,%3}, {%4,%5,%6,%7}, {%8,%9}, {%0,%1,%2,%3};"
        : "+f"(c[0]), "+f"(c[1]), "+f"(c[2]), "+f"(c[3])
        : "r"(a[0]), "r"(a[1]), "r"(a[2]), "r"(a[3]), "r"(b0), "r"(b1));
}

// ---------------- weight transpose + fp32->fp16 (vectorized writes) ----------
__global__ void transpose_f2h_k(const float* __restrict__ src, __half* __restrict__ dst,
                                int R, int C) {
    __shared__ float t[64][33];
    const int bx = blockIdx.x * 32, by = blockIdx.y * 64;
    const float* s = src + (size_t)blockIdx.z * R * C;
    __half* d = dst + (size_t)blockIdx.z * R * C;
    const int tx = threadIdx.x & 31;
    const int ty = threadIdx.x >> 5;
    #pragma unroll
    for (int i = 0; i < 8; i++)
        t[ty + i * 8][tx] = s[(size_t)(by + ty + i * 8) * C + bx + tx];
    __syncthreads();
    const int c  = threadIdx.x >> 3;
    const int r0 = (threadIdx.x & 7) * 8;
    __half2 h[4];
    #pragma unroll
    for (int k = 0; k < 4; k++)
        h[k] = __floats2half2_rn(t[r0 + 2 * k][c], t[r0 + 2 * k + 1][c]);
    *(uint4*)(d + (size_t)(bx + c) * R + by + r0) = *(uint4*)h;
}

__global__ void transpose_qkv_k(const float* __restrict__ q, const float* __restrict__ k,
                                const float* __restrict__ v, __half* __restrict__ dst) {
    __shared__ float t[64][33];
    const int z = blockIdx.z;
    const int slot = z / Lz, l = z % Lz;
    const float* s = (slot == 0 ? q : (slot == 1 ? k : v)) + (size_t)l * Hz * Hz;
    __half* d = dst + ((size_t)l * 3 + slot) * Hz * Hz;
    const int bx = blockIdx.x * 32, by = blockIdx.y * 64;
    const int tx = threadIdx.x & 31;
    const int ty = threadIdx.x >> 5;
    #pragma unroll
    for (int i = 0; i < 8; i++)
        t[ty + i * 8][tx] = s[(size_t)(by + ty + i * 8) * Hz + bx + tx];
    __syncthreads();
    const int c  = threadIdx.x >> 3;
    const int r0 = (threadIdx.x & 7) * 8;
    __half2 h[4];
    #pragma unroll
    for (int kk = 0; kk < 4; kk++)
        h[kk] = __floats2half2_rn(t[r0 + 2 * kk][c], t[r0 + 2 * kk + 1][c]);
    *(uint4*)(d + (size_t)(bx + c) * Hz + by + r0) = *(uint4*)h;
}

// ---------------- block reductions ------------------------------------------
__device__ __forceinline__ float bsum256(float v, float* sm) {
    #pragma unroll
    for (int o = 16; o; o >>= 1) v += __shfl_xor_sync(0xFFFFFFFFu, v, o);
    int t = threadIdx.x;
    if ((t & 31) == 0) sm[t >> 5] = v;
    __syncthreads();
    float r = sm[0];
    #pragma unroll
    for (int i = 1; i < 8; i++) r += sm[i];
    __syncthreads();
    return r;
}

__device__ __forceinline__ float bsum192(float v, float* sm) {
    #pragma unroll
    for (int o = 16; o; o >>= 1) v += __shfl_xor_sync(0xFFFFFFFFu, v, o);
    int t = threadIdx.x;
    if ((t & 31) == 0) sm[t >> 5] = v;
    __syncthreads();
    float r = sm[0] + sm[1] + sm[2] + sm[3] + sm[4] + sm[5];
    __syncthreads();
    return r;
}

// ---------------- embedding + LN ---------------------------------------------
__global__ void embed_ln_k(const int* __restrict__ ids,
                           const float* __restrict__ we,
                           const float* __restrict__ pe,
                           const float* __restrict__ te,
                           const float* __restrict__ g,
                           const float* __restrict__ b,
                           float* __restrict__ dF,
                           __half* __restrict__ dB) {
    __shared__ float sm[8];
    int row = blockIdx.x;
    int s_ = row & (Sz - 1);
    int id = ids[row];
    int t = threadIdx.x;
    float v[3];
    #pragma unroll
    for (int i = 0; i < 3; i++) {
        int col = t + i * 256;
        v[i] = we[(size_t)id * Hz + col] + pe[(size_t)(s_ + 2) * Hz + col] + te[col];
    }
    float mean = bsum256(v[0] + v[1] + v[2], sm) * (1.0f / Hz);
    float d0 = v[0] - mean, d1 = v[1] - mean, d2 = v[2] - mean;
    float var = bsum256(d0*d0 + d1*d1 + d2*d2, sm) * (1.0f / Hz);
    float rs = rsqrtf(var + 1e-5f);
    size_t base = (size_t)row * Hz;
    #pragma unroll
    for (int i = 0; i < 3; i++) {
        int col = t + i * 256;
        float y = (v[i] - mean) * rs * g[col] + b[col];
        dF[base + col] = y;
        dB[base + col] = __float2half_rn(y);
    }
}

// ---------------- fused split-K reduce + bias + fp32 residual + LayerNorm ----
// vectorized: 192 threads x float4 (768 cols). p2 may be null.
__global__ void __launch_bounds__(192) lnr_k(const float4* __restrict__ p0,
                                             const float4* __restrict__ p1,
                                             const float4* __restrict__ p2,
                                             const float4* __restrict__ bias,
                                             const float4* __restrict__ res,
                                             const float4* __restrict__ g,
                                             const float4* __restrict__ b,
                                             float4* __restrict__ dF,
                                             __half* __restrict__ dB) {
    __shared__ float sm[6];
    const size_t base = (size_t)blockIdx.x * 192;   // in float4 units
    const int t = threadIdx.x;
    float4 v = p0[base + t];
    {
        float4 q = p1[base + t];
        v.x += q.x; v.y += q.y; v.z += q.z; v.w += q.w;
    }
    if (p2) {
        float4 q = p2[base + t];
        v.x += q.x; v.y += q.y; v.z += q.z; v.w += q.w;
    }
    {
        float4 bi = bias[t];
        float4 r = res[base + t];
        v.x += bi.x + r.x; v.y += bi.y + r.y; v.z += bi.z + r.z; v.w += bi.w + r.w;
    }
    float mean = bsum192(v.x + v.y + v.z + v.w, sm) * (1.0f / Hz);
    float dx = v.x - mean, dy = v.y - mean, dz = v.z - mean, dw = v.w - mean;
    float var = bsum192(dx*dx + dy*dy + dz*dz + dw*dw, sm) * (1.0f / Hz);
    float rs = rsqrtf(var + 1e-5f);
    float4 g4 = g[t], b4 = b[t];
    float4 y;
    y.x = dx * rs * g4.x + b4.x;
    y.y = dy * rs * g4.y + b4.y;
    y.z = dz * rs * g4.z + b4.z;
    y.w = dw * rs * g4.w + b4.w;
    dF[base + t] = y;
    __half2 h[2];
    h[0] = __floats2half2_rn(y.x, y.y);
    h[1] = __floats2half2_rn(y.z, y.w);
    ((uint2*)dB)[base + t] = *(uint2*)h;
}

// ---------------- HMMA GEMM: 128x128 tile, 4 warps of 64x64, BK=64, 3-stage --
struct GP {
    const __half* A;
    const __half* Bt;
    const float* bias;
    const float* bias1;
    const float* bias2;
    float* outF;
    float* outF2;
    float* outF3;
    __half* outB;
    int K, lda, ldo;
};

#define GSMEM 110592

template<int EPI>
__global__ void __launch_bounds__(128, 2) hgemm_k(GP p) {
    extern __shared__ __align__(16) char smraw[];
    const int tid = threadIdx.x;
    const int wid = tid >> 5;
    const int wm = wid >> 1, wn = wid & 1;
    const int m0 = blockIdx.y * 128, n0 = blockIdx.x * 128;
    const int zi = blockIdx.z;

    const __half* Arow = p.A + (size_t)m0 * p.lda + (size_t)zi * p.K;
    const __half* Brow = p.Bt + (size_t)n0 * p.lda + (size_t)zi * p.K;
    const int K = p.K, KT = K >> 6, lda = p.lda;

    uint32_t sbase = (uint32_t)__cvta_generic_to_shared(smraw);

    auto issue = [&](int kt, int st) {
        const __half* as = Arow + kt * 64;
        const __half* bs = Brow + kt * 64;
        const uint32_t sa = sbase + st * 36864;
        const uint32_t sb = sa + 18432;
        #pragma unroll
        for (int i = 0; i < 8; i++) {
            int g = tid + i * 128;
            int r = g >> 3, c = g & 7;
            cpa16(sa + r * 144 + c * 16, as + (size_t)r * lda + c * 8);
            cpa16(sb + r * 144 + c * 16, bs + (size_t)r * lda + c * 8);
        }
    };

    issue(0, 0); cpa_commit();
    issue(1, 1); cpa_commit();

    wmma::fragment<wmma::accumulator, 16, 16, 16, float> acc[4][4];
    #pragma unroll
    for (int i = 0; i < 4; i++)
        #pragma unroll
        for (int j = 0; j < 4; j++) wmma::fill_fragment(acc[i][j], 0.0f);

    for (int kt = 0; kt < KT; kt++) {
        cpa_wait<1>();
        __syncthreads();
        if (kt + 2 < KT) issue(kt + 2, (kt + 2) % 3);
        cpa_commit();

        const int st = kt % 3;
        const __half* sA = (const __half*)(smraw + st * 36864);
        const __half* sB = sA + 9216;
        #pragma unroll
        for (int kk = 0; kk < 4; kk++) {
            wmma::fragment<wmma::matrix_a, 16, 16, 16, __half, wmma::row_major> af[4];
            #pragma unroll
            for (int i = 0; i < 4; i++)
                wmma::load_matrix_sync(af[i], sA + (wm * 64 + i * 16) * 72 + kk * 16, 72);
            wmma::fragment<wmma::matrix_b, 16, 16, 16, __half, wmma::col_major> bf[4];
            #pragma unroll
            for (int j = 0; j < 4; j++)
                wmma::load_matrix_sync(bf[j], sB + (wn * 64 + j * 16) * 72 + kk * 16, 72);
            #pragma unroll
            for (int i = 0; i < 4; i++)
                #pragma unroll
                for (int j = 0; j < 4; j++)
                    wmma::mma_sync(acc[i][j], af[i], bf[j], acc[i][j]);
        }
    }

    if (EPI == 3) {
        float* outp = (zi == 0) ? p.outF : ((zi == 1) ? p.outF2 : p.outF3);
        float* out = outp + (size_t)m0 * p.ldo + n0;
        #pragma unroll
        for (int i = 0; i < 4; i++)
            #pragma unroll
            for (int j = 0; j < 4; j++)
                wmma::store_matrix_sync(out + (size_t)(wm * 64 + i * 16) * p.ldo + wn * 64 + j * 16,
                                        acc[i][j], p.ldo, wmma::mem_row_major);
        return;
    }

    __syncthreads();
    float* epi = (float*)smraw;
    #pragma unroll
    for (int i = 0; i < 4; i++)
        #pragma unroll
        for (int j = 0; j < 4; j++)
            wmma::store_matrix_sync(epi + (wm * 64 + i * 16) * 132 + wn * 64 + j * 16,
                                    acc[i][j], 132, wmma::mem_row_major);
    __syncthreads();

    {
        const float* ep = epi + tid * 132;
        const int gm = m0 + tid;
        __half* orow = p.outB + (size_t)gm * p.ldo + n0;
        #pragma unroll 4
        for (int c0 = 0; c0 < 128; c0 += 8) {
            float f[8];
            #pragma unroll
            for (int j = 0; j < 8; j++) {
                int n = n0 + c0 + j;
                float bv;
                if (EPI == 0 && p.bias1) {
                    const float* bp = n < 768 ? p.bias : (n < 1536 ? p.bias1 : p.bias2);
                    bv = bp[n & 767];
                } else {
                    bv = p.bias[n];
                }
                f[j] = ep[c0 + j] + bv;
            }
            __half2 h[4];
            #pragma unroll
            for (int j = 0; j < 4; j++) h[j] = __floats2half2_rn(f[2*j], f[2*j+1]);
            *(uint4*)(orow + c0) = *(uint4*)h;
        }
    }
}

// ---------------- FFN1 GEMM: 64x128 tile, 4 warps of 32x64, BK=64, 2-stage ---
#define G64SMEM 55296

__global__ void __launch_bounds__(128, 3) hgemm64_k(GP p) {
    extern __shared__ __align__(16) char smraw[];
    const int tid = threadIdx.x;
    const int wid = tid >> 5;
    const int wm = wid >> 1, wn = wid & 1;
    const int m0 = blockIdx.y * 64, n0 = blockIdx.x * 128;

    const __half* Arow = p.A + (size_t)m0 * p.lda;
    const __half* Brow = p.Bt + (size_t)n0 * p.lda;
    const int K = p.K, KT = K >> 6, lda = p.lda;

    uint32_t sbase = (uint32_t)__cvta_generic_to_shared(smraw);

    auto issue = [&](int kt, int st) {
        const __half* as = Arow + kt * 64;
        const __half* bs = Brow + kt * 64;
        const uint32_t sa = sbase + st * 27648;
        const uint32_t sb = sa + 9216;
        #pragma unroll
        for (int i = 0; i < 4; i++) {
            int g = tid + i * 128;
            int r = g >> 3, c = g & 7;
            cpa16(sa + r * 144 + c * 16, as + (size_t)r * lda + c * 8);
        }
        #pragma unroll
        for (int i = 0; i < 8; i++) {
            int g = tid + i * 128;
            int r = g >> 3, c = g & 7;
            cpa16(sb + r * 144 + c * 16, bs + (size_t)r * lda + c * 8);
        }
    };

    issue(0, 0); cpa_commit();

    wmma::fragment<wmma::accumulator, 16, 16, 16, float> acc[2][4];
    #pragma unroll
    for (int i = 0; i < 2; i++)
        #pragma unroll
        for (int j = 0; j < 4; j++) wmma::fill_fragment(acc[i][j], 0.0f);

    for (int kt = 0; kt < KT; kt++) {
        cpa_wait<0>();
        __syncthreads();
        if (kt + 1 < KT) { issue(kt + 1, (kt + 1) & 1); cpa_commit(); }

        const int st = kt & 1;
        const __half* sA = (const __half*)(smraw + st * 27648);
        const __half* sB = sA + 4608;
        #pragma unroll
        for (int kk = 0; kk < 4; kk++) {
            wmma::fragment<wmma::matrix_a, 16, 16, 16, __half, wmma::row_major> af[2];
            #pragma unroll
            for (int i = 0; i < 2; i++)
                wmma::load_matrix_sync(af[i], sA + (wm * 32 + i * 16) * 72 + kk * 16, 72);
            wmma::fragment<wmma::matrix_b, 16, 16, 16, __half, wmma::col_major> bf[4];
            #pragma unroll
            for (int j = 0; j < 4; j++)
                wmma::load_matrix_sync(bf[j], sB + (wn * 64 + j * 16) * 72 + kk * 16, 72);
            #pragma unroll
            for (int i = 0; i < 2; i++)
                #pragma unroll
                for (int j = 0; j < 4; j++)
                    wmma::mma_sync(acc[i][j], af[i], bf[j], acc[i][j]);
        }
        __syncthreads();
    }

    float* epi = (float*)smraw;
    #pragma unroll
    for (int i = 0; i < 2; i++)
        #pragma unroll
        for (int j = 0; j < 4; j++)
            wmma::store_matrix_sync(epi + (wm * 32 + i * 16) * 132 + wn * 64 + j * 16,
                                    acc[i][j], 132, wmma::mem_row_major);
    __syncthreads();

    {
        const int r = tid >> 1;
        const int co = (tid & 1) * 64;
        const float* ep = epi + r * 132 + co;
        const int gm = m0 + r;
        const int gn0 = n0 + co;
        __half* orow = p.outB + (size_t)gm * p.ldo + gn0;
        #pragma unroll 4
        for (int c0 = 0; c0 < 64; c0 += 8) {
            float f[8];
            #pragma unroll
            for (int j = 0; j < 8; j++) f[j] = ep[c0 + j] + p.bias[gn0 + c0 + j];
            #pragma unroll
            for (int j = 0; j < 8; j++)
                f[j] = 0.5f * f[j] * (1.0f + erff(f[j] * 0.70710678118654752f));
            __half2 h[4];
            #pragma unroll
            for (int j = 0; j < 4; j++) h[j] = __floats2half2_rn(f[2*j], f[2*j+1]);
            *(uint4*)(orow + c0) = *(uint4*)h;
        }
    }
}

// ---------------- FA2-style flash attention (raw mma, register-resident) ------
#define FSMEM 55296

__global__ void __launch_bounds__(256, 2) flash_k(const __half* __restrict__ qkv,
                                                  __half* __restrict__ ctx) {
    extern __shared__ __align__(16) char sm[];
    __half* sQ = (__half*)sm;
    uint32_t sbase = (uint32_t)__cvta_generic_to_shared(sm);

    const int tid = threadIdx.x, lane = tid & 31, wid = tid >> 5;
    const int qt = blockIdx.x, z = blockIdx.y;
    const int b = z / NHz, h = z % NHz;

    const __half* Qp = qkv + (size_t)(b * Sz) * QLD + h * DHz;
    const __half* Kp = Qp + 768;
    const __half* Vp = Qp + 1536;

    #pragma unroll
    for (int s = 0; s < 4; s++) {
        int ch = tid + s * 256;
        int r = ch >> 3, c = (ch & 7) << 3;
        *(uint4*)(sQ + r * 72 + c) = *(const uint4*)(Qp + (size_t)(qt * 128 + r) * QLD + c);
    }

    auto issueKV = [&](int kt) {
        int st = kt & 1;
        uint32_t kb = sbase + 18432 + st * 18432;
        uint32_t vb = kb + 9216;
        #pragma unroll
        for (int i = 0; i < 2; i++) {
            int g = tid + i * 256;
            int r = g >> 3, c = g & 7;
            size_t go = (size_t)(kt * 64 + r) * QLD + c * 8;
            cpa16(kb + r * 144 + c * 16, Kp + go);
            cpa16(vb + r * 144 + c * 16, Vp + go);
        }
    };

    issueKV(0); cpa_commit();
    __syncthreads();

    const int m8 = lane & 7;
    const int g1 = ((lane >> 3) & 1) * 8;
    const int g2 = (lane >> 4) * 8;

    uint32_t qf[4][4];
    {
        const __half2 sc = __half2half2(__float2half_rn(0.125f));
        #pragma unroll
        for (int t = 0; t < 4; t++) {
            ldsm4(qf[t], sbase + (wid * 16 + g1 + m8) * 144 + (t * 16 + g2) * 2);
            #pragma unroll
            for (int j = 0; j < 4; j++) {
                __half2 v = __hmul2(*(__half2*)&qf[t][j], sc);
                qf[t][j] = *(uint32_t*)&v;
            }
        }
    }

    float oacc[8][4];
    #pragma unroll
    for (int j = 0; j < 8; j++) {
        oacc[j][0] = 0.0f; oacc[j][1] = 0.0f; oacc[j][2] = 0.0f; oacc[j][3] = 0.0f;
    }
    float mr0 = -1e30f, mr1 = -1e30f, lr0 = 0.0f, lr1 = 0.0f;

    for (int kt = 0; kt < 8; kt++) {
        cpa_wait<0>();
        __syncthreads();
        if (kt < 7) { issueKV(kt + 1); cpa_commit(); }
        const uint32_t kb = sbase + 18432 + (kt & 1) * 18432;
        const uint32_t vb = kb + 9216;

        float sacc[8][4];
        #pragma unroll
        for (int j = 0; j < 8; j++) {
            sacc[j][0] = 0.0f; sacc[j][1] = 0.0f; sacc[j][2] = 0.0f; sacc[j][3] = 0.0f;
        }
        #pragma unroll
        for (int t = 0; t < 4; t++) {
            #pragma unroll
            for (int u = 0; u < 4; u++) {
                uint32_t kf[4];
                ldsm4(kf, kb + (u * 16 + g2 + m8) * 144 + (t * 16 + g1) * 2);
                mma16816(sacc[2*u],     qf[t], kf[0], kf[1]);
                mma16816(sacc[2*u + 1], qf[t], kf[2], kf[3]);
            }
        }

        float mx0 = -1e30f, mx1 = -1e30f;
        #pragma unroll
        for (int j = 0; j < 8; j++) {
            mx0 = fmaxf(mx0, fmaxf(sacc[j][0], sacc[j][1]));
            mx1 = fmaxf(mx1, fmaxf(sacc[j][2], sacc[j][3]));
        }
        mx0 = fmaxf(mx0, __shfl_xor_sync(0xFFFFFFFFu, mx0, 1));
        mx0 = fmaxf(mx0, __shfl_xor_sync(0xFFFFFFFFu, mx0, 2));
        mx1 = fmaxf(mx1, __shfl_xor_sync(0xFFFFFFFFu, mx1, 1));
        mx1 = fmaxf(mx1, __shfl_xor_sync(0xFFFFFFFFu, mx1, 2));
        float mn0 = fmaxf(mr0, mx0), mn1 = fmaxf(mr1, mx1);
        float s0 = 0.0f, s1 = 0.0f;
        #pragma unroll
        for (int j = 0; j < 8; j++) {
            sacc[j][0] = __expf(sacc[j][0] - mn0);
            sacc[j][1] = __expf(sacc[j][1] - mn0);
            sacc[j][2] = __expf(sacc[j][2] - mn1);
            sacc[j][3] = __expf(sacc[j][3] - mn1);
            s0 += sacc[j][0] + sacc[j][1];
            s1 += sacc[j][2] + sacc[j][3];
        }
        s0 += __shfl_xor_sync(0xFFFFFFFFu, s0, 1);
        s0 += __shfl_xor_sync(0xFFFFFFFFu, s0, 2);
        s1 += __shfl_xor_sync(0xFFFFFFFFu, s1, 1);
        s1 += __shfl_xor_sync(0xFFFFFFFFu, s1, 2);
        float f0 = __expf(mr0 - mn0), f1 = __expf(mr1 - mn1);
        lr0 = lr0 * f0 + s0; lr1 = lr1 * f1 + s1;
        mr0 = mn0; mr1 = mn1;
        #pragma unroll
        for (int j = 0; j < 8; j++) {
            oacc[j][0] *= f0; oacc[j][1] *= f0;
            oacc[j][2] *= f1; oacc[j][3] *= f1;
        }

        #pragma unroll
        for (int t = 0; t < 4; t++) {
            uint32_t af[4];
            {
                __half2 a0 = __floats2half2_rn(sacc[2*t][0],     sacc[2*t][1]);
                __half2 a1 = __floats2half2_rn(sacc[2*t][2],     sacc[2*t][3]);
                __half2 a2 = __floats2half2_rn(sacc[2*t + 1][0], sacc[2*t + 1][1]);
                __half2 a3 = __floats2half2_rn(sacc[2*t + 1][2], sacc[2*t + 1][3]);
                af[0] = *(uint32_t*)&a0; af[1] = *(uint32_t*)&a1;
                af[2] = *(uint32_t*)&a2; af[3] = *(uint32_t*)&a3;
            }
            #pragma unroll
            for (int u = 0; u < 4; u++) {
                uint32_t vf[4];
                ldsm4t(vf, vb + (t * 16 + g1 + m8) * 144 + (u * 16 + g2) * 2);
                mma16816(oacc[2*u],     af, vf[0], vf[1]);
                mma16816(oacc[2*u + 1], af, vf[2], vf[3]);
            }
        }
    }

    float inv0 = 1.0f / lr0, inv1 = 1.0f / lr1;
    int row0 = qt * 128 + wid * 16 + (lane >> 2);
    __half* dst0 = ctx + ((size_t)(b * Sz) + row0) * Hz + h * DHz + (lane & 3) * 2;
    __half* dst1 = dst0 + 8 * Hz;
    #pragma unroll
    for (int j = 0; j < 8; j++) {
        __half2 o0 = __floats2half2_rn(oacc[j][0] * inv0, oacc[j][1] * inv0);
        __half2 o1 = __floats2half2_rn(oacc[j][2] * inv1, oacc[j][3] * inv1);
        *(__half2*)(dst0 + j * 8) = o0;
        *(__half2*)(dst1 + j * 8) = o1;
    }
}

// ---------------- host orchestration ----------------------------------------
extern "C" void kernel_launch(void* const* d_in, const int* in_sizes, int n_in,
                              void* d_out, int out_size) {
    const int*   ids   = (const int*)d_in[0];
    const float* word  = (const float*)d_in[1];
    const float* pos   = (const float*)d_in[2];
    const float* type0 = (const float*)d_in[3];
    const float* lneg  = (const float*)d_in[4];
    const float* lneb  = (const float*)d_in[5];
    const float* Wq    = (const float*)d_in[6];
    const float* bq    = (const float*)d_in[7];
    const float* Wk    = (const float*)d_in[8];
    const float* bk    = (const float*)d_in[9];
    const float* Wv    = (const float*)d_in[10];
    const float* bv    = (const float*)d_in[11];
    const float* Wo    = (const float*)d_in[12];
    const float* bo    = (const float*)d_in[13];
    const float* ln1g  = (const float*)d_in[14];
    const float* ln1b  = (const float*)d_in[15];
    const float* Wi    = (const float*)d_in[16];
    const float* bi    = (const float*)d_in[17];
    const float* Wo2   = (const float*)d_in[18];
    const float* bo2   = (const float*)d_in[19];
    const float* ln2g  = (const float*)d_in[20];
    const float* ln2b  = (const float*)d_in[21];

    float *x, *attn, *tmp, *tmp2, *tmp3;
    __half *xb, *attnb, *qkv, *ctx, *hh, *wqkvT, *woT, *wiT, *wo2T;
    cudaGetSymbolAddress((void**)&x,     g_x);
    cudaGetSymbolAddress((void**)&attn,  g_attn);
    cudaGetSymbolAddress((void**)&tmp,   g_tmp);
    cudaGetSymbolAddress((void**)&tmp2,  g_tmp2);
    cudaGetSymbolAddress((void**)&tmp3,  g_tmp3);
    cudaGetSymbolAddress((void**)&xb,    g_xb);
    cudaGetSymbolAddress((void**)&attnb, g_attnb);
    cudaGetSymbolAddress((void**)&qkv,   g_qkv);
    cudaGetSymbolAddress((void**)&ctx,   g_ctx);
    cudaGetSymbolAddress((void**)&hh,    g_h);
    cudaGetSymbolAddress((void**)&wqkvT, g_wqkvT);
    cudaGetSymbolAddress((void**)&woT,   g_woT);
    cudaGetSymbolAddress((void**)&wiT,   g_wiT);
    cudaGetSymbolAddress((void**)&wo2T,  g_wo2T);

    cudaFuncSetAttribute(hgemm_k<0>, cudaFuncAttributeMaxDynamicSharedMemorySize, GSMEM);
    cudaFuncSetAttribute(hgemm_k<3>, cudaFuncAttributeMaxDynamicSharedMemorySize, GSMEM);
    cudaFuncSetAttribute(hgemm64_k,  cudaFuncAttributeMaxDynamicSharedMemorySize, G64SMEM);
    cudaFuncSetAttribute(flash_k,    cudaFuncAttributeMaxDynamicSharedMemorySize, FSMEM);

    transpose_qkv_k<<<dim3(Hz/32, Hz/64, 3 * Lz), 256>>>(Wq, Wk, Wv, wqkvT);
    transpose_f2h_k<<<dim3(Hz/32, Hz/64, Lz), 256>>>(Wo, woT, Hz, Hz);
    transpose_f2h_k<<<dim3(Iz/32, Hz/64, Lz), 256>>>(Wi, wiT, Hz, Iz);
    transpose_f2h_k<<<dim3(Hz/32, Iz/64, Lz), 256>>>(Wo2, wo2T, Iz, Hz);
    embed_ln_k<<<Bz * Sz, 256>>>(ids, word, pos, type0, lneg, lneb, x, xb);

    const int M = Bz * Sz; // 8192
    for (int l = 0; l < Lz; l++) {
        // fused QKV projection
        {
            GP p{};
            p.A = xb;
            p.Bt = wqkvT + (size_t)l * 3 * Hz * Hz;
            p.bias = bq + l * Hz; p.bias1 = bk + l * Hz; p.bias2 = bv + l * Hz;
            p.outB = qkv; p.K = Hz; p.lda = Hz; p.ldo = QLD;
            hgemm_k<0><<<dim3(QLD / 128, M / 128, 1), 128, GSMEM>>>(p);
        }
        flash_k<<<dim3(Sz / 128, Bz * NHz), 256, FSMEM>>>(qkv, ctx);
        // O projection, split-K=2, raw fp32 partials
        {
            GP p{};
            p.A = ctx; p.Bt = woT + (size_t)l * Hz * Hz;
            p.outF = tmp; p.outF2 = tmp2;
            p.K = Hz / 2; p.lda = Hz; p.ldo = Hz;
            hgemm_k<3><<<dim3(Hz / 128, M / 128, 2), 128, GSMEM>>>(p);
        }
        // reduce(2) + bias + fp32 residual(x) + LN1 -> attn (fp32) + attnb (fp16)
        lnr_k<<<Bz * Sz, 192>>>((const float4*)tmp, (const float4*)tmp2, nullptr,
                                (const float4*)(bo + l * Hz), (const float4*)x,
                                (const float4*)(ln1g + l * Hz), (const float4*)(ln1b + l * Hz),
                                (float4*)attn, attnb);
        // FFN1 + GELU (64-row tiles, occ 3, wave-efficient)
        {
            GP p{};
            p.A = attnb; p.Bt = wiT + (size_t)l * Hz * Iz;
            p.bias = bi + l * Iz; p.outB = hh;
            p.K = Hz; p.lda = Hz; p.ldo = Iz;
            hgemm64_k<<<dim3(Iz / 128, M / 64), 128, G64SMEM>>>(p);
        }
        // FFN2, split-K=3, raw fp32 partials
        {
            GP p{};
            p.A = hh; p.Bt = wo2T + (size_t)l * Hz * Iz;
            p.outF = tmp; p.outF2 = tmp2; p.outF3 = tmp3;
            p.K = Iz / 3; p.lda = Iz; p.ldo = Hz;
            hgemm_k<3><<<dim3(Hz / 128, M / 128, 3), 128, GSMEM>>>(p);
        }
        float* outp = (l == Lz - 1) ? (float*)d_out : x;
        // reduce(3) + bias + fp32 residual(attn) + LN2 -> x (fp32) + xb (fp16)
        lnr_k<<<Bz * Sz, 192>>>((const float4*)tmp, (const float4*)tmp2, (const float4*)tmp3,
                                (const float4*)(bo2 + l * Hz), (const float4*)attn,
                                (const float4*)(ln2g + l * Hz), (const float4*)(ln2b + l * Hz),
                                (float4*)outp, xb);
    }
}